// round 1
// baseline (speedup 1.0000x reference)
#include <cuda_runtime.h>

#define NMAX   100000
#define EMAX   1200000
#define NGRAPH 64
#define D      64

// ---------------- device scratch (no allocations allowed) ----------------
__device__ __align__(16) float g_bufH[(size_t)NMAX * D];
__device__ __align__(16) float g_bufG[(size_t)NMAX * D];
__device__ float g_deg[NMAX];
__device__ float g_dinv[NMAX];
__device__ __align__(16) float g_pooled[NGRAPH * D];
__device__ float g_cnt[NGRAPH];
__device__ float g_sc1[D], g_sh1[D], g_sc2[D], g_sh2[D];

__device__ __forceinline__ void red_add_v4(float* addr, float4 v) {
    asm volatile("red.global.add.v4.f32 [%0], {%1,%2,%3,%4};"
                 :: "l"(addr), "f"(v.x), "f"(v.y), "f"(v.z), "f"(v.w)
                 : "memory");
}

// ---------------- init: zero agg buffer, deg=1 (self loop), pooled/cnt=0 ----
__global__ void k_init(int N) {
    size_t i = (size_t)blockIdx.x * blockDim.x + threadIdx.x;
    size_t total = (size_t)N * D;
    for (size_t t = i; t < total; t += (size_t)gridDim.x * blockDim.x)
        g_bufG[t] = 0.f;
    if (i < (size_t)N) g_deg[i] = 1.f;
    if (i < NGRAPH * D) g_pooled[i] = 0.f;
    if (i < NGRAPH) g_cnt[i] = 0.f;
}

__global__ void k_zeroH(int N) {
    size_t i = (size_t)blockIdx.x * blockDim.x + threadIdx.x;
    size_t total = (size_t)N * D;
    for (size_t t = i; t < total; t += (size_t)gridDim.x * blockDim.x)
        g_bufH[t] = 0.f;
}

// ---------------- degree via atomics over dst ----------------
__global__ void k_deg(const int* __restrict__ dst, int E) {
    int e = blockIdx.x * blockDim.x + threadIdx.x;
    if (e < E) atomicAdd(&g_deg[dst[e]], 1.0f);
}

// ---------------- dinv + folded BN params ----------------
__global__ void k_prep(const float* __restrict__ b1, const float* __restrict__ g1,
                       const float* __restrict__ be1, const float* __restrict__ m1,
                       const float* __restrict__ v1,
                       const float* __restrict__ b2, const float* __restrict__ g2,
                       const float* __restrict__ be2, const float* __restrict__ m2,
                       const float* __restrict__ v2, int N) {
    int t = blockIdx.x * blockDim.x + threadIdx.x;
    if (t < N) g_dinv[t] = rsqrtf(g_deg[t]);
    if (t < D) {
        float s1 = g1[t] * rsqrtf(v1[t] + 1e-5f);
        g_sc1[t] = s1;
        g_sh1[t] = (b1[t] - m1[t]) * s1 + be1[t];
        float s2 = g2[t] * rsqrtf(v2[t] + 1e-5f);
        g_sc2[t] = s2;
        g_sh2[t] = (b2[t] - m2[t]) * s2 + be2[t];
    }
}

// ---------------- GEMM: C[N,64] = A[N,64] @ W[64,64] ----------------
// 256 threads, 64 rows/block, 4x4 register tile per thread, smem-staged A & W.
__global__ void __launch_bounds__(256) k_gemm(const float* __restrict__ A,
                                              const float* __restrict__ W,
                                              float* __restrict__ C, int N) {
    __shared__ float Ws[D * D];      // 16 KB, row-major [k][c]
    __shared__ float As[64 * 65];    // padded, [r][k]
    int tid = threadIdx.x;
    int row0 = blockIdx.x * 64;

    float4* Ws4 = (float4*)Ws;
    const float4* W4 = (const float4*)W;
#pragma unroll
    for (int i = 0; i < 4; i++) Ws4[tid + i * 256] = W4[tid + i * 256];

#pragma unroll
    for (int i = 0; i < 4; i++) {
        int idx = tid + i * 256;      // 0..1023
        int r = idx >> 4, c4 = idx & 15;
        float4 a = make_float4(0.f, 0.f, 0.f, 0.f);
        if (row0 + r < N)
            a = __ldg((const float4*)(A + (size_t)(row0 + r) * D) + c4);
        As[r * 65 + c4 * 4 + 0] = a.x;
        As[r * 65 + c4 * 4 + 1] = a.y;
        As[r * 65 + c4 * 4 + 2] = a.z;
        As[r * 65 + c4 * 4 + 3] = a.w;
    }
    __syncthreads();

    int tx = tid & 15, ty = tid >> 4;
    float acc[4][4];
#pragma unroll
    for (int i = 0; i < 4; i++)
#pragma unroll
        for (int j = 0; j < 4; j++) acc[i][j] = 0.f;

    const float* Ar0 = &As[(ty * 4 + 0) * 65];
    const float* Ar1 = &As[(ty * 4 + 1) * 65];
    const float* Ar2 = &As[(ty * 4 + 2) * 65];
    const float* Ar3 = &As[(ty * 4 + 3) * 65];

#pragma unroll
    for (int k = 0; k < 64; k++) {
        float4 w = Ws4[k * 16 + tx];
        float a0 = Ar0[k], a1 = Ar1[k], a2 = Ar2[k], a3 = Ar3[k];
        acc[0][0] += a0 * w.x; acc[0][1] += a0 * w.y; acc[0][2] += a0 * w.z; acc[0][3] += a0 * w.w;
        acc[1][0] += a1 * w.x; acc[1][1] += a1 * w.y; acc[1][2] += a1 * w.z; acc[1][3] += a1 * w.w;
        acc[2][0] += a2 * w.x; acc[2][1] += a2 * w.y; acc[2][2] += a2 * w.z; acc[2][3] += a2 * w.w;
        acc[3][0] += a3 * w.x; acc[3][1] += a3 * w.y; acc[3][2] += a3 * w.z; acc[3][3] += a3 * w.w;
    }

#pragma unroll
    for (int i = 0; i < 4; i++) {
        int r = row0 + ty * 4 + i;
        if (r < N) {
            float4 o = make_float4(acc[i][0], acc[i][1], acc[i][2], acc[i][3]);
            *((float4*)(C + (size_t)r * D) + tx) = o;
        }
    }
}

// ---------------- edge scatter: agg[dst] += h[src]*dinv[src]*dinv[dst] -----
// 16 threads per edge, float4 vector atomics.
__global__ void k_scatter(const int* __restrict__ src, const int* __restrict__ dst,
                          const float* __restrict__ h, float* __restrict__ agg, int E) {
    long long t = (long long)blockIdx.x * blockDim.x + threadIdx.x;
    int e = (int)(t >> 4);
    if (e >= E) return;
    int lane = (int)(t & 15);
    int s = __ldg(src + e), d = __ldg(dst + e);
    float norm = __ldg(&g_dinv[s]) * __ldg(&g_dinv[d]);
    float4 v = __ldg((const float4*)(h + (size_t)s * D) + lane);
    v.x *= norm; v.y *= norm; v.z *= norm; v.w *= norm;
    red_add_v4(agg + (size_t)d * D + lane * 4, v);
}

// ---------------- epilogue 1: h = relu(bn(agg + h*dinv^2)), in place -------
__global__ void k_epi1(const float* __restrict__ agg, float* __restrict__ h, int N) {
    int t = blockIdx.x * blockDim.x + threadIdx.x;
    if (t >= N * 16) return;
    int n = t >> 4, c4 = t & 15;
    float di = g_dinv[n];
    float di2 = di * di;
    float4 a = ((const float4*)agg)[(size_t)n * 16 + c4];
    float4 hv = ((const float4*)h)[(size_t)n * 16 + c4];
    int c = c4 * 4;
    float4 y;
    y.x = fmaxf(0.f, (a.x + hv.x * di2) * g_sc1[c + 0] + g_sh1[c + 0]);
    y.y = fmaxf(0.f, (a.y + hv.y * di2) * g_sc1[c + 1] + g_sh1[c + 1]);
    y.z = fmaxf(0.f, (a.z + hv.z * di2) * g_sc1[c + 2] + g_sh1[c + 2]);
    y.w = fmaxf(0.f, (a.w + hv.w * di2) * g_sc1[c + 3] + g_sh1[c + 3]);
    ((float4*)h)[(size_t)n * 16 + c4] = y;
}

// ---------------- epilogue 2 + mean-pool accumulation ----------------------
__global__ void k_epi2pool(const float* __restrict__ agg, const float* __restrict__ h,
                           const int* __restrict__ batch, int N) {
    int t = blockIdx.x * blockDim.x + threadIdx.x;
    if (t >= N * 16) return;
    int n = t >> 4, c4 = t & 15;
    float di = g_dinv[n];
    float di2 = di * di;
    float4 a = ((const float4*)agg)[(size_t)n * 16 + c4];
    float4 hv = ((const float4*)h)[(size_t)n * 16 + c4];
    int c = c4 * 4;
    float4 y;
    y.x = fmaxf(0.f, (a.x + hv.x * di2) * g_sc2[c + 0] + g_sh2[c + 0]);
    y.y = fmaxf(0.f, (a.y + hv.y * di2) * g_sc2[c + 1] + g_sh2[c + 1]);
    y.z = fmaxf(0.f, (a.z + hv.z * di2) * g_sc2[c + 2] + g_sh2[c + 2]);
    y.w = fmaxf(0.f, (a.w + hv.w * di2) * g_sc2[c + 3] + g_sh2[c + 3]);
    int g = batch[n];
    red_add_v4(&g_pooled[g * D + c4 * 4], y);
    if (c4 == 0) atomicAdd(&g_cnt[g], 1.0f);
}

// ---------------- classifier: out[g][o] = (pooled[g]/cnt[g]) @ Wc + bc -----
__global__ void k_cls(const float* __restrict__ Wc, const float* __restrict__ bc,
                      float* __restrict__ out) {
    int t = threadIdx.x;
    if (t >= NGRAPH * 2) return;
    int g = t >> 1, o = t & 1;
    float inv = 1.f / fmaxf(g_cnt[g], 1.f);
    float s = 0.f;
#pragma unroll
    for (int d = 0; d < D; d++) s += g_pooled[g * D + d] * Wc[d * 2 + o];
    out[t] = s * inv + bc[o];
}

// ---------------- host orchestration ----------------
extern "C" void kernel_launch(void* const* d_in, const int* in_sizes, int n_in,
                              void* d_out, int out_size) {
    const float* x   = (const float*)d_in[0];
    const int*   ei  = (const int*)d_in[1];
    const int*   bat = (const int*)d_in[2];
    const float* W1  = (const float*)d_in[3];
    const float* b1  = (const float*)d_in[4];
    const float* g1  = (const float*)d_in[5];
    const float* be1 = (const float*)d_in[6];
    const float* m1  = (const float*)d_in[7];
    const float* v1  = (const float*)d_in[8];
    const float* W2  = (const float*)d_in[9];
    const float* b2  = (const float*)d_in[10];
    const float* g2  = (const float*)d_in[11];
    const float* be2 = (const float*)d_in[12];
    const float* m2  = (const float*)d_in[13];
    const float* v2  = (const float*)d_in[14];
    const float* Wc  = (const float*)d_in[15];
    const float* bc  = (const float*)d_in[16];
    float* out = (float*)d_out;

    int N = in_sizes[0] / D;
    int E = in_sizes[1] / 2;
    const int* src = ei;
    const int* dst = ei + E;

    float *bufH, *bufG;
    cudaGetSymbolAddress((void**)&bufH, g_bufH);
    cudaGetSymbolAddress((void**)&bufG, g_bufG);

    int nb_edges   = (E + 255) / 256;
    int nb_scatter = (int)(((long long)E * 16 + 255) / 256);
    int nb_node16  = (N * 16 + 255) / 256;
    int nb_gemm    = (N + 63) / 64;
    int nb_node    = (N + 255) / 256;

    k_init<<<512, 256>>>(N);
    k_deg<<<nb_edges, 256>>>(dst, E);
    k_prep<<<nb_node, 256>>>(b1, g1, be1, m1, v1, b2, g2, be2, m2, v2, N);

    // layer 1
    k_gemm<<<nb_gemm, 256>>>(x, W1, bufH, N);
    k_scatter<<<nb_scatter, 256>>>(src, dst, bufH, bufG, E);
    k_epi1<<<nb_node16, 256>>>(bufG, bufH, N);

    // layer 2
    k_gemm<<<nb_gemm, 256>>>(bufH, W2, bufG, N);
    k_zeroH<<<512, 256>>>(N);
    k_scatter<<<nb_scatter, 256>>>(src, dst, bufG, bufH, E);
    k_epi2pool<<<nb_node16, 256>>>(bufH, bufG, bat, N);

    // classifier
    k_cls<<<1, 128>>>(Wc, bc, out);
}

// round 2
// speedup vs baseline: 1.3801x; 1.3801x over previous
#include <cuda_runtime.h>

#define NMAX   100000
#define EMAX   1200000
#define NGRAPH 64
#define D      64
#define NBLK_SCAN 128   // >= ceil(NMAX/1024)

// ---------------- device scratch (no allocations allowed) ----------------
__device__ __align__(16) float g_bufH[(size_t)NMAX * D];
__device__ __align__(16) float g_bufG[(size_t)NMAX * D];
__device__ float g_dinv[NMAX];
__device__ __align__(16) float g_pooled[NGRAPH * D];
__device__ float g_cnt[NGRAPH];
__device__ float g_sc1[D], g_sh1[D], g_sc2[D], g_sh2[D];

// CSR scratch
__device__ int g_cntI[NMAX];
__device__ int g_offs[NMAX + 1];
__device__ int g_cursor[NMAX];
__device__ int g_csrc[EMAX];
__device__ int g_bsum[NBLK_SCAN];

__device__ __forceinline__ void red_add_v4(float* addr, float4 v) {
    asm volatile("red.global.add.v4.f32 [%0], {%1,%2,%3,%4};"
                 :: "l"(addr), "f"(v.x), "f"(v.y), "f"(v.z), "f"(v.w)
                 : "memory");
}

// ---------------- init ----------------
__global__ void k_init(int N) {
    int i = blockIdx.x * blockDim.x + threadIdx.x;
    if (i < N) g_cntI[i] = 0;
    if (i < NGRAPH * D) g_pooled[i] = 0.f;
    if (i < NGRAPH) g_cnt[i] = 0.f;
}

// ---------------- in-degree histogram ----------------
__global__ void k_cnt(const int* __restrict__ dst, int E) {
    int e = blockIdx.x * blockDim.x + threadIdx.x;
    if (e < E) atomicAdd(&g_cntI[dst[e]], 1);
}

// ---------------- dinv + folded BN params ----------------
__global__ void k_prep(const float* __restrict__ b1, const float* __restrict__ g1,
                       const float* __restrict__ be1, const float* __restrict__ m1,
                       const float* __restrict__ v1,
                       const float* __restrict__ b2, const float* __restrict__ g2,
                       const float* __restrict__ be2, const float* __restrict__ m2,
                       const float* __restrict__ v2, int N) {
    int t = blockIdx.x * blockDim.x + threadIdx.x;
    if (t < N) g_dinv[t] = rsqrtf((float)g_cntI[t] + 1.0f);
    if (t < D) {
        float s1 = g1[t] * rsqrtf(v1[t] + 1e-5f);
        g_sc1[t] = s1;
        g_sh1[t] = (b1[t] - m1[t]) * s1 + be1[t];
        float s2 = g2[t] * rsqrtf(v2[t] + 1e-5f);
        g_sc2[t] = s2;
        g_sh2[t] = (b2[t] - m2[t]) * s2 + be2[t];
    }
}

// ---------------- exclusive scan over g_cntI -> g_offs (3 kernels) --------
__global__ void k_scan1(int N) {
    __shared__ int wsum[8];
    int t = threadIdx.x, b = blockIdx.x;
    int base = b * 1024 + t * 4;
    int v0 = 0, v1 = 0, v2 = 0, v3 = 0;
    if (base + 0 < N) v0 = g_cntI[base + 0];
    if (base + 1 < N) v1 = g_cntI[base + 1];
    if (base + 2 < N) v2 = g_cntI[base + 2];
    if (base + 3 < N) v3 = g_cntI[base + 3];
    int s = v0 + v1 + v2 + v3;
    int lane = t & 31, w = t >> 5;
    int inc = s;
#pragma unroll
    for (int o = 1; o < 32; o <<= 1) {
        int y = __shfl_up_sync(0xffffffff, inc, o);
        if (lane >= o) inc += y;
    }
    if (lane == 31) wsum[w] = inc;
    __syncthreads();
    if (t == 0) {
        int run = 0;
#pragma unroll
        for (int i = 0; i < 8; i++) { int x = wsum[i]; wsum[i] = run; run += x; }
        g_bsum[b] = run;
    }
    __syncthreads();
    int ex = wsum[w] + inc - s;
    if (base + 0 < N) { g_offs[base + 0] = ex; ex += v0; }
    if (base + 1 < N) { g_offs[base + 1] = ex; ex += v1; }
    if (base + 2 < N) { g_offs[base + 2] = ex; ex += v2; }
    if (base + 3 < N) { g_offs[base + 3] = ex; }
}

__global__ void k_scan2(int nblk) {
    __shared__ int ws[4];
    int t = threadIdx.x;              // 128 threads
    int v = (t < nblk) ? g_bsum[t] : 0;
    int lane = t & 31, w = t >> 5;
    int inc = v;
#pragma unroll
    for (int o = 1; o < 32; o <<= 1) {
        int y = __shfl_up_sync(0xffffffff, inc, o);
        if (lane >= o) inc += y;
    }
    if (lane == 31) ws[w] = inc;
    __syncthreads();
    if (t == 0) {
        int run = 0;
#pragma unroll
        for (int i = 0; i < 4; i++) { int x = ws[i]; ws[i] = run; run += x; }
    }
    __syncthreads();
    int excl = ws[w] + inc - v;
    if (t < nblk) g_bsum[t] = excl;
}

__global__ void k_scan3(int N, int E) {
    int i = blockIdx.x * blockDim.x + threadIdx.x;
    if (i < N) {
        int o = g_offs[i] + g_bsum[i >> 10];
        g_offs[i] = o;
        g_cursor[i] = o;
    }
    if (i == 0) g_offs[N] = E;
}

// ---------------- fill CSR: src indices grouped by dst ----------------
__global__ void k_fill(const int* __restrict__ src, const int* __restrict__ dst, int E) {
    int e = blockIdx.x * blockDim.x + threadIdx.x;
    if (e < E) {
        int d = dst[e];
        int p = atomicAdd(&g_cursor[d], 1);
        g_csrc[p] = src[e];
    }
}

// ---------------- GEMM: C[N,64] = (A[N,64] @ W[64,64]) * dinv[row] --------
__global__ void __launch_bounds__(256) k_gemm(const float* __restrict__ A,
                                              const float* __restrict__ W,
                                              float* __restrict__ C, int N) {
    __shared__ float Ws[D * D];      // [k][c]
    __shared__ float As[64 * 65];    // [r][k]
    int tid = threadIdx.x;
    int row0 = blockIdx.x * 64;

    float4* Ws4 = (float4*)Ws;
    const float4* W4 = (const float4*)W;
#pragma unroll
    for (int i = 0; i < 4; i++) Ws4[tid + i * 256] = W4[tid + i * 256];

#pragma unroll
    for (int i = 0; i < 4; i++) {
        int idx = tid + i * 256;
        int r = idx >> 4, c4 = idx & 15;
        float4 a = make_float4(0.f, 0.f, 0.f, 0.f);
        if (row0 + r < N)
            a = __ldg((const float4*)(A + (size_t)(row0 + r) * D) + c4);
        As[r * 65 + c4 * 4 + 0] = a.x;
        As[r * 65 + c4 * 4 + 1] = a.y;
        As[r * 65 + c4 * 4 + 2] = a.z;
        As[r * 65 + c4 * 4 + 3] = a.w;
    }
    __syncthreads();

    int tx = tid & 15, ty = tid >> 4;
    float acc[4][4];
#pragma unroll
    for (int i = 0; i < 4; i++)
#pragma unroll
        for (int j = 0; j < 4; j++) acc[i][j] = 0.f;

    const float* Ar0 = &As[(ty * 4 + 0) * 65];
    const float* Ar1 = &As[(ty * 4 + 1) * 65];
    const float* Ar2 = &As[(ty * 4 + 2) * 65];
    const float* Ar3 = &As[(ty * 4 + 3) * 65];

#pragma unroll
    for (int k = 0; k < 64; k++) {
        float4 w = Ws4[k * 16 + tx];
        float a0 = Ar0[k], a1 = Ar1[k], a2 = Ar2[k], a3 = Ar3[k];
        acc[0][0] += a0 * w.x; acc[0][1] += a0 * w.y; acc[0][2] += a0 * w.z; acc[0][3] += a0 * w.w;
        acc[1][0] += a1 * w.x; acc[1][1] += a1 * w.y; acc[1][2] += a1 * w.z; acc[1][3] += a1 * w.w;
        acc[2][0] += a2 * w.x; acc[2][1] += a2 * w.y; acc[2][2] += a2 * w.z; acc[2][3] += a2 * w.w;
        acc[3][0] += a3 * w.x; acc[3][1] += a3 * w.y; acc[3][2] += a3 * w.z; acc[3][3] += a3 * w.w;
    }

#pragma unroll
    for (int i = 0; i < 4; i++) {
        int r = row0 + ty * 4 + i;
        if (r < N) {
            float di = g_dinv[r];
            float4 o = make_float4(acc[i][0] * di, acc[i][1] * di,
                                   acc[i][2] * di, acc[i][3] * di);
            *((float4*)(C + (size_t)r * D) + tx) = o;
        }
    }
}

// ---------------- gather + epilogue 1: out = relu(bn(dinv[d]*sum(hpre))) ---
__global__ void __launch_bounds__(256) k_agg1(const float* __restrict__ hpre,
                                              float* __restrict__ out, int N) {
    int t = blockIdx.x * blockDim.x + threadIdx.x;
    int d = t >> 4;
    if (d >= N) return;
    int c4 = t & 15;
    const float4* hp4 = (const float4*)hpre;
    float4 acc = hp4[(size_t)d * 16 + c4];   // self loop term
    int beg = g_offs[d], end = g_offs[d + 1];
    int j = beg;
    for (; j + 1 < end; j += 2) {
        int s0 = __ldg(&g_csrc[j]);
        int s1 = __ldg(&g_csrc[j + 1]);
        float4 a = __ldg(&hp4[(size_t)s0 * 16 + c4]);
        float4 b = __ldg(&hp4[(size_t)s1 * 16 + c4]);
        acc.x += a.x + b.x; acc.y += a.y + b.y;
        acc.z += a.z + b.z; acc.w += a.w + b.w;
    }
    if (j < end) {
        int s0 = __ldg(&g_csrc[j]);
        float4 a = __ldg(&hp4[(size_t)s0 * 16 + c4]);
        acc.x += a.x; acc.y += a.y; acc.z += a.z; acc.w += a.w;
    }
    float di = g_dinv[d];
    int c = c4 * 4;
    float4 y;
    y.x = fmaxf(0.f, acc.x * di * g_sc1[c + 0] + g_sh1[c + 0]);
    y.y = fmaxf(0.f, acc.y * di * g_sc1[c + 1] + g_sh1[c + 1]);
    y.z = fmaxf(0.f, acc.z * di * g_sc1[c + 2] + g_sh1[c + 2]);
    y.w = fmaxf(0.f, acc.w * di * g_sc1[c + 3] + g_sh1[c + 3]);
    ((float4*)out)[(size_t)d * 16 + c4] = y;
}

// ---------------- gather + epilogue 2 + mean-pool accumulation -------------
__global__ void __launch_bounds__(256) k_agg2(const float* __restrict__ hpre,
                                              const int* __restrict__ batch, int N) {
    int t = blockIdx.x * blockDim.x + threadIdx.x;
    int d = t >> 4;
    if (d >= N) return;
    int c4 = t & 15;
    const float4* hp4 = (const float4*)hpre;
    float4 acc = hp4[(size_t)d * 16 + c4];
    int beg = g_offs[d], end = g_offs[d + 1];
    int j = beg;
    for (; j + 1 < end; j += 2) {
        int s0 = __ldg(&g_csrc[j]);
        int s1 = __ldg(&g_csrc[j + 1]);
        float4 a = __ldg(&hp4[(size_t)s0 * 16 + c4]);
        float4 b = __ldg(&hp4[(size_t)s1 * 16 + c4]);
        acc.x += a.x + b.x; acc.y += a.y + b.y;
        acc.z += a.z + b.z; acc.w += a.w + b.w;
    }
    if (j < end) {
        int s0 = __ldg(&g_csrc[j]);
        float4 a = __ldg(&hp4[(size_t)s0 * 16 + c4]);
        acc.x += a.x; acc.y += a.y; acc.z += a.z; acc.w += a.w;
    }
    float di = g_dinv[d];
    int c = c4 * 4;
    float4 y;
    y.x = fmaxf(0.f, acc.x * di * g_sc2[c + 0] + g_sh2[c + 0]);
    y.y = fmaxf(0.f, acc.y * di * g_sc2[c + 1] + g_sh2[c + 1]);
    y.z = fmaxf(0.f, acc.z * di * g_sc2[c + 2] + g_sh2[c + 2]);
    y.w = fmaxf(0.f, acc.w * di * g_sc2[c + 3] + g_sh2[c + 3]);
    int g = batch[d];
    red_add_v4(&g_pooled[g * D + c4 * 4], y);
    if (c4 == 0) atomicAdd(&g_cnt[g], 1.0f);
}

// ---------------- classifier ----------------
__global__ void k_cls(const float* __restrict__ Wc, const float* __restrict__ bc,
                      float* __restrict__ out) {
    int t = threadIdx.x;
    if (t >= NGRAPH * 2) return;
    int g = t >> 1, o = t & 1;
    float inv = 1.f / fmaxf(g_cnt[g], 1.f);
    float s = 0.f;
#pragma unroll
    for (int d = 0; d < D; d++) s += g_pooled[g * D + d] * Wc[d * 2 + o];
    out[t] = s * inv + bc[o];
}

// ---------------- host orchestration ----------------
extern "C" void kernel_launch(void* const* d_in, const int* in_sizes, int n_in,
                              void* d_out, int out_size) {
    const float* x   = (const float*)d_in[0];
    const int*   ei  = (const int*)d_in[1];
    const int*   bat = (const int*)d_in[2];
    const float* W1  = (const float*)d_in[3];
    const float* b1  = (const float*)d_in[4];
    const float* g1  = (const float*)d_in[5];
    const float* be1 = (const float*)d_in[6];
    const float* m1  = (const float*)d_in[7];
    const float* v1  = (const float*)d_in[8];
    const float* W2  = (const float*)d_in[9];
    const float* b2  = (const float*)d_in[10];
    const float* g2  = (const float*)d_in[11];
    const float* be2 = (const float*)d_in[12];
    const float* m2  = (const float*)d_in[13];
    const float* v2  = (const float*)d_in[14];
    const float* Wc  = (const float*)d_in[15];
    const float* bc  = (const float*)d_in[16];
    float* out = (float*)d_out;

    int N = in_sizes[0] / D;
    int E = in_sizes[1] / 2;
    const int* src = ei;
    const int* dst = ei + E;

    float *bufH, *bufG;
    cudaGetSymbolAddress((void**)&bufH, g_bufH);
    cudaGetSymbolAddress((void**)&bufG, g_bufG);

    int nb_edges  = (E + 255) / 256;
    int nb_node   = (N + 255) / 256;
    int nb_node16 = (int)(((long long)N * 16 + 255) / 256);
    int nb_gemm   = (N + 63) / 64;
    int nblk_scan = (N + 1023) / 1024;

    k_init<<<nb_node, 256>>>(N);
    k_cnt<<<nb_edges, 256>>>(dst, E);
    k_prep<<<nb_node, 256>>>(b1, g1, be1, m1, v1, b2, g2, be2, m2, v2, N);

    // CSR build
    k_scan1<<<nblk_scan, 256>>>(N);
    k_scan2<<<1, 128>>>(nblk_scan);
    k_scan3<<<nb_node, 256>>>(N, E);
    k_fill<<<nb_edges, 256>>>(src, dst, E);

    // layer 1
    k_gemm<<<nb_gemm, 256>>>(x, W1, bufH, N);
    k_agg1<<<nb_node16, 256>>>(bufH, bufG, N);

    // layer 2
    k_gemm<<<nb_gemm, 256>>>(bufG, W2, bufH, N);
    k_agg2<<<nb_node16, 256>>>(bufH, bat, N);

    // classifier
    k_cls<<<1, 128>>>(Wc, bc, out);
}

// round 3
// speedup vs baseline: 1.3978x; 1.0129x over previous
#include <cuda_runtime.h>

#define NMAX   100000
#define EMAX   1200000
#define NGRAPH 64
#define D      64
#define NBLK_SCAN 128   // >= ceil(NMAX/1024)

// ---------------- device scratch (no allocations allowed) ----------------
// INVARIANT: g_cntI, g_pooled, g_cnt are ZERO at entry to every call
// (zero-initialized at load; each call re-zeroes them after last use).
__device__ __align__(16) float g_bufH[(size_t)NMAX * D];
__device__ __align__(16) float g_bufG[(size_t)NMAX * D];
__device__ float g_dinv[NMAX];
__device__ __align__(16) float g_pooled[NGRAPH * D];
__device__ float g_cnt[NGRAPH];
__device__ float g_sc1[D], g_sh1[D], g_sc2[D], g_sh2[D];

__device__ int g_cntI[NMAX];
__device__ int g_offs[NMAX + 1];
__device__ int g_cursor[NMAX];
__device__ int g_csrc[EMAX];
__device__ int g_bsum[NBLK_SCAN];

__device__ __forceinline__ void red_add_v4(float* addr, float4 v) {
    asm volatile("red.global.add.v4.f32 [%0], {%1,%2,%3,%4};"
                 :: "l"(addr), "f"(v.x), "f"(v.y), "f"(v.z), "f"(v.w)
                 : "memory");
}

// ---------------- in-degree histogram (g_cntI is pre-zeroed) --------------
__global__ void k_cnt(const int* __restrict__ dst, int E) {
    int e = blockIdx.x * blockDim.x + threadIdx.x;
    if (e < E) atomicAdd(&g_cntI[dst[e]], 1);
}

// ---------------- scan pass 1 ----------------
__global__ void k_scan1(int N) {
    __shared__ int wsum[8];
    int t = threadIdx.x, b = blockIdx.x;
    int base = b * 1024 + t * 4;
    int v0 = 0, v1 = 0, v2 = 0, v3 = 0;
    if (base + 0 < N) v0 = g_cntI[base + 0];
    if (base + 1 < N) v1 = g_cntI[base + 1];
    if (base + 2 < N) v2 = g_cntI[base + 2];
    if (base + 3 < N) v3 = g_cntI[base + 3];
    int s = v0 + v1 + v2 + v3;
    int lane = t & 31, w = t >> 5;
    int inc = s;
#pragma unroll
    for (int o = 1; o < 32; o <<= 1) {
        int y = __shfl_up_sync(0xffffffff, inc, o);
        if (lane >= o) inc += y;
    }
    if (lane == 31) wsum[w] = inc;
    __syncthreads();
    if (t == 0) {
        int run = 0;
#pragma unroll
        for (int i = 0; i < 8; i++) { int x = wsum[i]; wsum[i] = run; run += x; }
        g_bsum[b] = run;
    }
    __syncthreads();
    int ex = wsum[w] + inc - s;
    if (base + 0 < N) { g_offs[base + 0] = ex; ex += v0; }
    if (base + 1 < N) { g_offs[base + 1] = ex; ex += v1; }
    if (base + 2 < N) { g_offs[base + 2] = ex; ex += v2; }
    if (base + 3 < N) { g_offs[base + 3] = ex; }
}

// ---------------- scan pass 2 (block sums) ----------------
__global__ void k_scan2(int nblk) {
    __shared__ int ws[4];
    int t = threadIdx.x;              // 128 threads
    int v = (t < nblk) ? g_bsum[t] : 0;
    int lane = t & 31, w = t >> 5;
    int inc = v;
#pragma unroll
    for (int o = 1; o < 32; o <<= 1) {
        int y = __shfl_up_sync(0xffffffff, inc, o);
        if (lane >= o) inc += y;
    }
    if (lane == 31) ws[w] = inc;
    __syncthreads();
    if (t == 0) {
        int run = 0;
#pragma unroll
        for (int i = 0; i < 4; i++) { int x = ws[i]; ws[i] = run; run += x; }
    }
    __syncthreads();
    int excl = ws[w] + inc - v;
    if (t < nblk) g_bsum[t] = excl;
}

// ---------------- scan pass 3 + dinv + BN fold + cntI reset ----------------
__global__ void k_scan3(const float* __restrict__ b1, const float* __restrict__ g1,
                        const float* __restrict__ be1, const float* __restrict__ m1,
                        const float* __restrict__ v1,
                        const float* __restrict__ b2, const float* __restrict__ g2,
                        const float* __restrict__ be2, const float* __restrict__ m2,
                        const float* __restrict__ v2, int N, int E) {
    int i = blockIdx.x * blockDim.x + threadIdx.x;
    if (i < N) {
        int o = g_offs[i] + g_bsum[i >> 10];
        g_offs[i] = o;
        g_cursor[i] = o;
        g_dinv[i] = rsqrtf((float)g_cntI[i] + 1.0f);
        g_cntI[i] = 0;                     // restore invariant for next call
    }
    if (i == 0) g_offs[N] = E;
    if (i < D) {
        float s1 = g1[i] * rsqrtf(v1[i] + 1e-5f);
        g_sc1[i] = s1;
        g_sh1[i] = (b1[i] - m1[i]) * s1 + be1[i];
        float s2 = g2[i] * rsqrtf(v2[i] + 1e-5f);
        g_sc2[i] = s2;
        g_sh2[i] = (b2[i] - m2[i]) * s2 + be2[i];
    }
}

// ---------------- fill CSR ----------------
__global__ void k_fill(const int* __restrict__ src, const int* __restrict__ dst, int E) {
    int e = blockIdx.x * blockDim.x + threadIdx.x;
    if (e < E) {
        int d = dst[e];
        int p = atomicAdd(&g_cursor[d], 1);
        g_csrc[p] = src[e];
    }
}

// ---------------- GEMM: C[N,64] = (A @ W) * dinv[row], float4 inner loop ---
#define GEMM_ROW(ai, i)                                                           \
    acc[i][0] = fmaf(ai.w, w3.x, fmaf(ai.z, w2.x, fmaf(ai.y, w1.x, fmaf(ai.x, w0.x, acc[i][0])))); \
    acc[i][1] = fmaf(ai.w, w3.y, fmaf(ai.z, w2.y, fmaf(ai.y, w1.y, fmaf(ai.x, w0.y, acc[i][1])))); \
    acc[i][2] = fmaf(ai.w, w3.z, fmaf(ai.z, w2.z, fmaf(ai.y, w1.z, fmaf(ai.x, w0.z, acc[i][2])))); \
    acc[i][3] = fmaf(ai.w, w3.w, fmaf(ai.z, w2.w, fmaf(ai.y, w1.w, fmaf(ai.x, w0.w, acc[i][3]))));

__global__ void __launch_bounds__(256) k_gemm(const float* __restrict__ A,
                                              const float* __restrict__ W,
                                              float* __restrict__ C, int N) {
    __shared__ __align__(16) float Ws[D * D];      // [k][c]
    __shared__ __align__(16) float As[64 * 68];    // [r][k], stride 68 (16B-mult)
    int tid = threadIdx.x;
    int row0 = blockIdx.x * 64;

    float4* Ws4 = (float4*)Ws;
    const float4* W4 = (const float4*)W;
#pragma unroll
    for (int i = 0; i < 4; i++) Ws4[tid + i * 256] = W4[tid + i * 256];

#pragma unroll
    for (int i = 0; i < 4; i++) {
        int idx = tid + i * 256;
        int r = idx >> 4, c4 = idx & 15;
        float4 a = make_float4(0.f, 0.f, 0.f, 0.f);
        if (row0 + r < N)
            a = __ldg((const float4*)(A + (size_t)(row0 + r) * D) + c4);
        ((float4*)&As[r * 68])[c4] = a;
    }
    __syncthreads();

    int tx = tid & 15, ty = tid >> 4;
    float acc[4][4];
#pragma unroll
    for (int i = 0; i < 4; i++)
#pragma unroll
        for (int j = 0; j < 4; j++) acc[i][j] = 0.f;

    const float4* A0 = (const float4*)&As[(ty * 4 + 0) * 68];
    const float4* A1 = (const float4*)&As[(ty * 4 + 1) * 68];
    const float4* A2 = (const float4*)&As[(ty * 4 + 2) * 68];
    const float4* A3 = (const float4*)&As[(ty * 4 + 3) * 68];

#pragma unroll
    for (int k4 = 0; k4 < 16; k4++) {
        float4 w0 = Ws4[(4 * k4 + 0) * 16 + tx];
        float4 w1 = Ws4[(4 * k4 + 1) * 16 + tx];
        float4 w2 = Ws4[(4 * k4 + 2) * 16 + tx];
        float4 w3 = Ws4[(4 * k4 + 3) * 16 + tx];
        float4 a0 = A0[k4], a1 = A1[k4], a2 = A2[k4], a3 = A3[k4];
        GEMM_ROW(a0, 0)
        GEMM_ROW(a1, 1)
        GEMM_ROW(a2, 2)
        GEMM_ROW(a3, 3)
    }

#pragma unroll
    for (int i = 0; i < 4; i++) {
        int r = row0 + ty * 4 + i;
        if (r < N) {
            float di = g_dinv[r];
            float4 o = make_float4(acc[i][0] * di, acc[i][1] * di,
                                   acc[i][2] * di, acc[i][3] * di);
            *((float4*)(C + (size_t)r * D) + tx) = o;
        }
    }
}

// ---------------- gather core (unroll 4 for MLP) ----------------
__device__ __forceinline__ float4 gather_row(const float4* __restrict__ hp4,
                                             int d, int c4) {
    float4 acc = hp4[(size_t)d * 16 + c4];   // self-loop term
    int beg = g_offs[d], end = g_offs[d + 1];
    int j = beg;
    for (; j + 3 < end; j += 4) {
        int s0 = __ldg(&g_csrc[j + 0]);
        int s1 = __ldg(&g_csrc[j + 1]);
        int s2 = __ldg(&g_csrc[j + 2]);
        int s3 = __ldg(&g_csrc[j + 3]);
        float4 a = __ldg(&hp4[(size_t)s0 * 16 + c4]);
        float4 b = __ldg(&hp4[(size_t)s1 * 16 + c4]);
        float4 c = __ldg(&hp4[(size_t)s2 * 16 + c4]);
        float4 e = __ldg(&hp4[(size_t)s3 * 16 + c4]);
        acc.x += (a.x + b.x) + (c.x + e.x);
        acc.y += (a.y + b.y) + (c.y + e.y);
        acc.z += (a.z + b.z) + (c.z + e.z);
        acc.w += (a.w + b.w) + (c.w + e.w);
    }
    for (; j < end; j++) {
        int s0 = __ldg(&g_csrc[j]);
        float4 a = __ldg(&hp4[(size_t)s0 * 16 + c4]);
        acc.x += a.x; acc.y += a.y; acc.z += a.z; acc.w += a.w;
    }
    return acc;
}

// ---------------- gather + epilogue 1 ----------------
__global__ void __launch_bounds__(256) k_agg1(const float* __restrict__ hpre,
                                              float* __restrict__ out, int N) {
    int t = blockIdx.x * blockDim.x + threadIdx.x;
    int d = t >> 4;
    if (d >= N) return;
    int c4 = t & 15;
    float4 acc = gather_row((const float4*)hpre, d, c4);
    float di = g_dinv[d];
    int c = c4 * 4;
    float4 y;
    y.x = fmaxf(0.f, acc.x * di * g_sc1[c + 0] + g_sh1[c + 0]);
    y.y = fmaxf(0.f, acc.y * di * g_sc1[c + 1] + g_sh1[c + 1]);
    y.z = fmaxf(0.f, acc.z * di * g_sc1[c + 2] + g_sh1[c + 2]);
    y.w = fmaxf(0.f, acc.w * di * g_sc1[c + 3] + g_sh1[c + 3]);
    ((float4*)out)[(size_t)d * 16 + c4] = y;
}

// ---------------- gather + epilogue 2 + mean-pool ----------------
__global__ void __launch_bounds__(256) k_agg2(const float* __restrict__ hpre,
                                              const int* __restrict__ batch, int N) {
    int t = blockIdx.x * blockDim.x + threadIdx.x;
    int d = t >> 4;
    if (d >= N) return;
    int c4 = t & 15;
    float4 acc = gather_row((const float4*)hpre, d, c4);
    float di = g_dinv[d];
    int c = c4 * 4;
    float4 y;
    y.x = fmaxf(0.f, acc.x * di * g_sc2[c + 0] + g_sh2[c + 0]);
    y.y = fmaxf(0.f, acc.y * di * g_sc2[c + 1] + g_sh2[c + 1]);
    y.z = fmaxf(0.f, acc.z * di * g_sc2[c + 2] + g_sh2[c + 2]);
    y.w = fmaxf(0.f, acc.w * di * g_sc2[c + 3] + g_sh2[c + 3]);
    int g = batch[d];
    red_add_v4(&g_pooled[g * D + c4 * 4], y);
    if (c4 == 0) atomicAdd(&g_cnt[g], 1.0f);
}

// ---------------- classifier + restore pooled/cnt invariant ----------------
__global__ void k_cls(const float* __restrict__ Wc, const float* __restrict__ bc,
                      float* __restrict__ out) {
    int t = threadIdx.x;          // 128 threads == NGRAPH*2
    int g = t >> 1, o = t & 1;
    float inv = 1.f / fmaxf(g_cnt[g], 1.f);
    float s = 0.f;
#pragma unroll
    for (int d = 0; d < D; d++) s += g_pooled[g * D + d] * Wc[d * 2 + o];
    float res = s * inv + bc[o];
    __syncthreads();              // all reads of g_pooled/g_cnt done
    for (int i = t; i < NGRAPH * D; i += 128) g_pooled[i] = 0.f;
    if (t < NGRAPH) g_cnt[t] = 0.f;
    out[t] = res;
}

// ---------------- host orchestration ----------------
extern "C" void kernel_launch(void* const* d_in, const int* in_sizes, int n_in,
                              void* d_out, int out_size) {
    const float* x   = (const float*)d_in[0];
    const int*   ei  = (const int*)d_in[1];
    const int*   bat = (const int*)d_in[2];
    const float* W1  = (const float*)d_in[3];
    const float* b1  = (const float*)d_in[4];
    const float* g1  = (const float*)d_in[5];
    const float* be1 = (const float*)d_in[6];
    const float* m1  = (const float*)d_in[7];
    const float* v1  = (const float*)d_in[8];
    const float* W2  = (const float*)d_in[9];
    const float* b2  = (const float*)d_in[10];
    const float* g2  = (const float*)d_in[11];
    const float* be2 = (const float*)d_in[12];
    const float* m2  = (const float*)d_in[13];
    const float* v2  = (const float*)d_in[14];
    const float* Wc  = (const float*)d_in[15];
    const float* bc  = (const float*)d_in[16];
    float* out = (float*)d_out;

    int N = in_sizes[0] / D;
    int E = in_sizes[1] / 2;
    const int* src = ei;
    const int* dst = ei + E;

    float *bufH, *bufG;
    cudaGetSymbolAddress((void**)&bufH, g_bufH);
    cudaGetSymbolAddress((void**)&bufG, g_bufG);

    int nb_edges  = (E + 255) / 256;
    int nb_node   = (N + 255) / 256;
    int nb_node16 = (int)(((long long)N * 16 + 255) / 256);
    int nb_gemm   = (N + 63) / 64;
    int nblk_scan = (N + 1023) / 1024;

    // CSR build (g_cntI zero at entry by invariant)
    k_cnt<<<nb_edges, 256>>>(dst, E);
    k_scan1<<<nblk_scan, 256>>>(N);
    k_scan2<<<1, 128>>>(nblk_scan);
    k_scan3<<<nb_node, 256>>>(b1, g1, be1, m1, v1, b2, g2, be2, m2, v2, N, E);
    k_fill<<<nb_edges, 256>>>(src, dst, E);

    // layer 1
    k_gemm<<<nb_gemm, 256>>>(x, W1, bufH, N);
    k_agg1<<<nb_node16, 256>>>(bufH, bufG, N);

    // layer 2
    k_gemm<<<nb_gemm, 256>>>(bufG, W2, bufH, N);
    k_agg2<<<nb_node16, 256>>>(bufH, bat, N);

    // classifier (+ restores pooled/cnt invariant)
    k_cls<<<1, 128>>>(Wc, bc, out);
}